// round 12
// baseline (speedup 1.0000x reference)
#include <cuda_runtime.h>
#include <cuda_bf16.h>
#include <cstdint>

// ---------------------------------------------------------------------------
// Problem constants
// ---------------------------------------------------------------------------
#define B_    256
#define T_    512
#define S_    256
#define L_    36
#define DIN_  8
#define OUT_  10
#define W_    256
#define NBLK  128        // persistent grid (<=148 SMs -> one wave, co-resident)
#define NW3   (S_ * L_)  // 9216

// M-phase smem layout (bytes) inside dynamic smem
#define AST32       20            // u32 stride per A row (40 bf16, conflict-free)
#define BST32       20
#define OFF_AS_H    0
#define OFF_AS_L    10240
#define OFF_BS_H    20480
#define OFF_BS_L    32000
#define OFF_LSS     43520
#define OFF_BSH     61952
#define SMEM_BYTES  62528

// ---------------------------------------------------------------------------
// Device scratch (allocation-free: __device__ globals)
// ---------------------------------------------------------------------------
__device__ float    g_h[B_ * S_];
__device__ __align__(16) __nv_bfloat16 g_z2h[B_ * W_];
__device__ __align__(16) __nv_bfloat16 g_z2l[B_ * W_];
__device__ __align__(16) __nv_bfloat16 g_w3h[NW3 * W_];   // 4.7 MB
__device__ __align__(16) __nv_bfloat16 g_w3l[NW3 * W_];
__device__ float    g_hidden[(T_ + 1) * B_ * S_];          // ~134 MB
__device__ unsigned g_bar;

// ---------------------------------------------------------------------------
// Math helpers
// ---------------------------------------------------------------------------
__device__ __forceinline__ float softplus_f(float x) {
    return (x > 0.f) ? (x + log1pf(__expf(-x))) : log1pf(__expf(x));
}
__device__ __forceinline__ float tanh_f(float x) {
    float e = __expf(2.f * x);
    return 1.f - __fdividef(2.f, e + 1.f);
}

// m16n8k16 bf16 MMA, fp32 accumulate (legacy tensor path on sm_103a)
__device__ __forceinline__ void mma_bf16(float* c, const unsigned* a,
                                         unsigned b0, unsigned b1) {
    asm volatile(
        "mma.sync.aligned.m16n8k16.row.col.f32.bf16.bf16.f32 "
        "{%0,%1,%2,%3}, {%4,%5,%6,%7}, {%8,%9}, {%0,%1,%2,%3};"
        : "+f"(c[0]), "+f"(c[1]), "+f"(c[2]), "+f"(c[3])
        : "r"(a[0]), "r"(a[1]), "r"(a[2]), "r"(a[3]), "r"(b0), "r"(b1));
}

// ---------------------------------------------------------------------------
// Software grid barrier (all NBLK blocks co-resident).
// ---------------------------------------------------------------------------
__device__ __forceinline__ void grid_barrier(unsigned target) {
    __syncthreads();
    if (threadIdx.x == 0) {
        __threadfence();
        atomicAdd(&g_bar, 1u);
        while (*((volatile unsigned*)&g_bar) < target) { __nanosleep(32); }
        __threadfence();
    }
    __syncthreads();
}

// ---------------------------------------------------------------------------
// Generic 4-row x (256 -> 256) dense layer (NT dot, W row-major [out][in]).
// ---------------------------------------------------------------------------
__device__ __forceinline__ void layer256(const float* __restrict__ in_s,
                                         float* __restrict__ out_s,
                                         const float* __restrict__ W,
                                         const float* __restrict__ bias,
                                         float* __restrict__ wtile,
                                         int tid, bool do_softplus)
{
    const int lane = tid & 31;
    const int warp = tid >> 5;
    const int r    = warp >> 1;
    const int half = warp & 1;
    int col[4];
#pragma unroll
    for (int j = 0; j < 4; ++j) col[j] = lane + 32 * half + 64 * j;

    float acc[4] = {0.f, 0.f, 0.f, 0.f};

    for (int kc = 0; kc < 8; ++kc) {
        __syncthreads();
#pragma unroll
        for (int u = 0; u < 8; ++u) {
            int e  = tid + 256 * u;
            int w  = e >> 3;
            int k4 = (e & 7) << 2;
            float4 v = *reinterpret_cast<const float4*>(W + w * 256 + kc * 32 + k4);
            *reinterpret_cast<float4*>(wtile + w * 36 + k4) = v;
        }
        __syncthreads();
#pragma unroll
        for (int kg = 0; kg < 8; ++kg) {
            float4 a = *reinterpret_cast<const float4*>(in_s + r * 256 + kc * 32 + kg * 4);
#pragma unroll
            for (int j = 0; j < 4; ++j) {
                float4 b = *reinterpret_cast<const float4*>(wtile + col[j] * 36 + kg * 4);
                acc[j] = fmaf(a.x, b.x, acc[j]);
                acc[j] = fmaf(a.y, b.y, acc[j]);
                acc[j] = fmaf(a.z, b.z, acc[j]);
                acc[j] = fmaf(a.w, b.w, acc[j]);
            }
        }
    }
    __syncthreads();
#pragma unroll
    for (int j = 0; j < 4; ++j) {
        float v = acc[j] + __ldg(bias + col[j]);
        if (do_softplus) v = softplus_f(v);
        out_s[r * 256 + col[j]] = v;
    }
}

// ---------------------------------------------------------------------------
// W3 split kernel (runs once per call): w = hi + lo in bf16.
// ---------------------------------------------------------------------------
__global__ void __launch_bounds__(256)
split_w3_kernel(const float* __restrict__ vW3)
{
    int i = blockIdx.x * 256 + threadIdx.x;   // grid = NW3 (9216) blocks
    float w = vW3[i];
    __nv_bfloat16 hi = __float2bfloat16(w);
    float lo = w - __bfloat162float(hi);
    g_w3h[i] = hi;
    g_w3l[i] = __float2bfloat16(lo);
}

// ---------------------------------------------------------------------------
// Init kernel: h0 = initMLP(x0) -> g_h, g_hidden[0]; resets g_bar.
// ---------------------------------------------------------------------------
__global__ void __launch_bounds__(256)
init_kernel(const float* __restrict__ x0,
            const float* __restrict__ iW1, const float* __restrict__ ib1,
            const float* __restrict__ iW2, const float* __restrict__ ib2,
            const float* __restrict__ iW3, const float* __restrict__ ib3)
{
    __shared__ __align__(16) float wtile[256 * 36];
    __shared__ __align__(16) float buf0[4 * 256];
    __shared__ __align__(16) float buf1[4 * 256];
    __shared__ float sx0[4 * 8];

    const int tid  = threadIdx.x;
    const int row0 = blockIdx.x * 4;

    if (blockIdx.x == 0 && tid == 0) g_bar = 0u;

    if (tid < 32) sx0[tid] = x0[row0 * DIN_ + tid];
#pragma unroll
    for (int u = 0; u < 8; ++u) wtile[tid + 256 * u] = iW1[tid + 256 * u];
    __syncthreads();

    {
        const int lane = tid & 31, warp = tid >> 5;
        const int r = warp >> 1, half = warp & 1;
#pragma unroll
        for (int j = 0; j < 4; ++j) {
            int c = lane + 32 * half + 64 * j;
            float acc = 0.f;
#pragma unroll
            for (int k = 0; k < 8; ++k)
                acc = fmaf(sx0[r * 8 + k], wtile[c * 8 + k], acc);
            buf0[r * 256 + c] = softplus_f(acc + __ldg(ib1 + c));
        }
    }
    layer256(buf0, buf1, iW2, ib2, wtile, tid, true);
    layer256(buf1, buf0, iW3, ib3, wtile, tid, false);
    __syncthreads();
#pragma unroll
    for (int u = 0; u < 4; ++u) {
        int e = tid + 256 * u;
        float v = buf0[e];
        g_h[row0 * 256 + e] = v;
        g_hidden[row0 * 256 + e] = v;
    }
}

// ---------------------------------------------------------------------------
// Persistent step kernel. grid = 128 x 256, dynamic smem SMEM_BYTES.
//
// Phase Z (blocks 0..63): z2 = sp(sp(h W1^T+b1) W2^T+b2); store bf16 hi/lo.
// Phase M (all blocks): C = z2 @ W3^T via bf16-split mma.sync (3 terms);
//   tanh + bias + l-contraction epilogue; h update; hidden store.
//   Block tile 128 rows x 144 cols; warp = 32 rows x 72 cols (2x9 m16n8).
// ---------------------------------------------------------------------------
__global__ void __launch_bounds__(256, 1)
step_kernel(const float* __restrict__ vW1, const float* __restrict__ vb1,
            const float* __restrict__ vW2, const float* __restrict__ vb2,
            const float* __restrict__ vb3, const float* __restrict__ logsigs)
{
    extern __shared__ __align__(16) unsigned char smem_raw[];

    const int tid = threadIdx.x;
    const int bid = blockIdx.x;

    // --- Z-phase carve (f32) ---
    float* wtile = reinterpret_cast<float*>(smem_raw);            // 9216 f32
    float* buf0  = wtile + 9216;                                  // 1024
    float* buf1  = wtile + 10240;                                 // 1024

    // --- M-phase carve ---
    unsigned* As_h = reinterpret_cast<unsigned*>(smem_raw + OFF_AS_H);  // 128x20
    unsigned* As_l = reinterpret_cast<unsigned*>(smem_raw + OFF_AS_L);
    unsigned* Bs_h = reinterpret_cast<unsigned*>(smem_raw + OFF_BS_H);  // 144x20
    unsigned* Bs_l = reinterpret_cast<unsigned*>(smem_raw + OFF_BS_L);
    float*    lss  = reinterpret_cast<float*>(smem_raw + OFF_LSS);      // 128x36
    float*    bsh  = reinterpret_cast<float*>(smem_raw + OFF_BSH);      // 144

    const unsigned* z2h32 = reinterpret_cast<const unsigned*>(g_z2h);   // [256][128]
    const unsigned* z2l32 = reinterpret_cast<const unsigned*>(g_z2l);
    const unsigned* w3h32 = reinterpret_cast<const unsigned*>(g_w3h);   // [9216][128]
    const unsigned* w3l32 = reinterpret_cast<const unsigned*>(g_w3l);

    // --- M-phase geometry ---
    const int lane = tid & 31;
    const int wrp  = tid >> 5;
    const int mg   = wrp & 3;          // m-group: 32 rows
    const int nh   = wrp >> 2;         // n-half: 72 cols
    const int gr   = lane >> 2;
    const int lq   = lane & 3;
    const int row0m = (bid & 1) * 128;
    const int n0    = (bid >> 1) * 144;
    const int s0    = (bid >> 1) * 4;
    const int nh72  = nh * 72;

    // staging assignments
    const int st_ar = tid >> 1;             // A row 0..127
    const int st_ak = (tid & 1) * 8;        // u32 offset {0,8}
    int  sb_r[3], sb_k[3]; bool sb_on[3];
#pragma unroll
    for (int u = 0; u < 3; ++u) {
        int idx  = tid + 256 * u;
        sb_on[u] = (idx < 576);
        sb_r[u]  = idx >> 2;                // B row 0..143
        sb_k[u]  = (idx & 3) * 4;           // u32 offset {0,4,8,12}
    }

    unsigned tgt = 0u;

    for (int t = 0; t < T_; ++t) {
        // =================== Phase Z (blocks 0..63) =======================
        if (bid < 64) {
            const int row0 = bid * 4;
#pragma unroll
            for (int u = 0; u < 4; ++u) {
                int e = tid + 256 * u;
                buf0[e] = g_h[row0 * 256 + e];
            }
            layer256(buf0, buf1, vW1, vb1, wtile, tid, true);
            layer256(buf1, buf0, vW2, vb2, wtile, tid, true);
            __syncthreads();
#pragma unroll
            for (int u = 0; u < 4; ++u) {
                int e = tid + 256 * u;
                float v = buf0[e];
                __nv_bfloat16 hi = __float2bfloat16(v);
                float lo = v - __bfloat162float(hi);
                g_z2h[row0 * 256 + e] = hi;
                g_z2l[row0 * 256 + e] = __float2bfloat16(lo);
            }
        }
        tgt += NBLK; grid_barrier(tgt);

        // =================== Phase M (all blocks) =========================
        for (int idx = tid; idx < 128 * 36; idx += 256) {
            int rb = idx / 36;
            int l  = idx - rb * 36;
            lss[idx] = logsigs[((size_t)(row0m + rb) * T_ + t) * L_ + l];
        }
        if (tid < 144) bsh[tid] = __ldg(vb3 + n0 + tid);

        float acc[2][9][4];
#pragma unroll
        for (int mf = 0; mf < 2; ++mf)
#pragma unroll
            for (int nf = 0; nf < 9; ++nf)
#pragma unroll
                for (int c = 0; c < 4; ++c) acc[mf][nf][c] = 0.f;

        // prefetch chunk 0 (k32 = 16 u32 per row)
        uint4 pAh[2], pAl[2], pBh[3], pBl[3];
        {
            const unsigned* ph = &z2h32[(row0m + st_ar) * 128 + st_ak];
            const unsigned* pl = &z2l32[(row0m + st_ar) * 128 + st_ak];
            pAh[0] = *reinterpret_cast<const uint4*>(ph);
            pAh[1] = *reinterpret_cast<const uint4*>(ph + 4);
            pAl[0] = *reinterpret_cast<const uint4*>(pl);
            pAl[1] = *reinterpret_cast<const uint4*>(pl + 4);
#pragma unroll
            for (int u = 0; u < 3; ++u)
                if (sb_on[u]) {
                    pBh[u] = *reinterpret_cast<const uint4*>(
                        &w3h32[(size_t)(n0 + sb_r[u]) * 128 + sb_k[u]]);
                    pBl[u] = *reinterpret_cast<const uint4*>(
                        &w3l32[(size_t)(n0 + sb_r[u]) * 128 + sb_k[u]]);
                }
        }

        for (int kc = 0; kc < 8; ++kc) {
            __syncthreads();   // previous compute done reading tiles
            *reinterpret_cast<uint4*>(&As_h[st_ar * AST32 + st_ak])     = pAh[0];
            *reinterpret_cast<uint4*>(&As_h[st_ar * AST32 + st_ak + 4]) = pAh[1];
            *reinterpret_cast<uint4*>(&As_l[st_ar * AST32 + st_ak])     = pAl[0];
            *reinterpret_cast<uint4*>(&As_l[st_ar * AST32 + st_ak + 4]) = pAl[1];
#pragma unroll
            for (int u = 0; u < 3; ++u)
                if (sb_on[u]) {
                    *reinterpret_cast<uint4*>(&Bs_h[sb_r[u] * BST32 + sb_k[u]]) = pBh[u];
                    *reinterpret_cast<uint4*>(&Bs_l[sb_r[u] * BST32 + sb_k[u]]) = pBl[u];
                }
            if (kc < 7) {
                const int ko = (kc + 1) * 16;
                const unsigned* ph = &z2h32[(row0m + st_ar) * 128 + ko + st_ak];
                const unsigned* pl = &z2l32[(row0m + st_ar) * 128 + ko + st_ak];
                pAh[0] = *reinterpret_cast<const uint4*>(ph);
                pAh[1] = *reinterpret_cast<const uint4*>(ph + 4);
                pAl[0] = *reinterpret_cast<const uint4*>(pl);
                pAl[1] = *reinterpret_cast<const uint4*>(pl + 4);
#pragma unroll
                for (int u = 0; u < 3; ++u)
                    if (sb_on[u]) {
                        pBh[u] = *reinterpret_cast<const uint4*>(
                            &w3h32[(size_t)(n0 + sb_r[u]) * 128 + ko + sb_k[u]]);
                        pBl[u] = *reinterpret_cast<const uint4*>(
                            &w3l32[(size_t)(n0 + sb_r[u]) * 128 + ko + sb_k[u]]);
                    }
            }
            __syncthreads();   // tiles ready

#pragma unroll
            for (int h = 0; h < 2; ++h) {            // two k16 halves
                const int kb = h * 8 + lq;
                unsigned ah[2][4], al[2][4];
#pragma unroll
                for (int mf = 0; mf < 2; ++mf) {
                    const int r0 = mg * 32 + mf * 16 + gr;
                    ah[mf][0] = As_h[r0 * AST32 + kb];
                    ah[mf][1] = As_h[(r0 + 8) * AST32 + kb];
                    ah[mf][2] = As_h[r0 * AST32 + kb + 4];
                    ah[mf][3] = As_h[(r0 + 8) * AST32 + kb + 4];
                    al[mf][0] = As_l[r0 * AST32 + kb];
                    al[mf][1] = As_l[(r0 + 8) * AST32 + kb];
                    al[mf][2] = As_l[r0 * AST32 + kb + 4];
                    al[mf][3] = As_l[(r0 + 8) * AST32 + kb + 4];
                }
#pragma unroll
                for (int nf = 0; nf < 9; ++nf) {
                    const int cb = (nh72 + nf * 8 + gr) * BST32 + kb;
                    unsigned bh0 = Bs_h[cb], bh1 = Bs_h[cb + 4];
                    unsigned bl0 = Bs_l[cb], bl1 = Bs_l[cb + 4];
#pragma unroll
                    for (int mf = 0; mf < 2; ++mf) {
                        mma_bf16(acc[mf][nf], ah[mf], bh0, bh1);  // hi*hi
                        mma_bf16(acc[mf][nf], ah[mf], bl0, bl1);  // hi*lo
                        mma_bf16(acc[mf][nf], al[mf], bh0, bh1);  // lo*hi
                    }
                }
            }
        }

        // ---- epilogue: bias + tanh + contract l, per MMA fragment layout ----
#pragma unroll
        for (int mf = 0; mf < 2; ++mf) {
            const int r0 = mg * 32 + mf * 16 + gr;   // local rows
            const int r1 = r0 + 8;
            float p0[2] = {0.f, 0.f}, p1[2] = {0.f, 0.f};
#pragma unroll
            for (int nf = 0; nf < 9; ++nf) {
#pragma unroll
                for (int c = 0; c < 2; ++c) {
                    int nl = nh72 + nf * 8 + 2 * lq + c;   // col in [0,144)
                    int l  = nl, sl = 0;
                    if (l >= 72) l -= 72;
                    if (l >= 36) { l -= 36; sl = 1; }
                    const float bj = bsh[nl];
                    const float v0 = tanh_f(acc[mf][nf][c]     + bj);
                    const float v1 = tanh_f(acc[mf][nf][2 + c] + bj);
                    p0[sl] = fmaf(v0, lss[r0 * 36 + l], p0[sl]);
                    p1[sl] = fmaf(v1, lss[r1 * 36 + l], p1[sl]);
                }
            }
#pragma unroll
            for (int sl = 0; sl < 2; ++sl) {
                p0[sl] += __shfl_xor_sync(0xffffffffu, p0[sl], 1);
                p0[sl] += __shfl_xor_sync(0xffffffffu, p0[sl], 2);
                p1[sl] += __shfl_xor_sync(0xffffffffu, p1[sl], 1);
                p1[sl] += __shfl_xor_sync(0xffffffffu, p1[sl], 2);
            }
            if (lq == 0) {
                const int b0g = row0m + r0;
                const int b1g = row0m + r1;
#pragma unroll
                for (int sl = 0; sl < 2; ++sl) {
                    const int sg = s0 + nh * 2 + sl;
                    float h0 = g_h[b0g * 256 + sg] + p0[sl];
                    float h1 = g_h[b1g * 256 + sg] + p1[sl];
                    g_h[b0g * 256 + sg] = h0;
                    g_h[b1g * 256 + sg] = h1;
                    g_hidden[(size_t)(t + 1) * (B_ * S_) + b0g * 256 + sg] = h0;
                    g_hidden[(size_t)(t + 1) * (B_ * S_) + b1g * 256 + sg] = h1;
                }
            }
        }
        tgt += NBLK; grid_barrier(tgt);
    }
}

// ---------------------------------------------------------------------------
// Readout: out[b,t,o] = sum_s hidden[t,b,s] * ro_W[o,s] + ro_b[o]
// ---------------------------------------------------------------------------
__global__ void __launch_bounds__(256)
readout_kernel(const float* __restrict__ roW, const float* __restrict__ rob,
               float* __restrict__ out)
{
    __shared__ float ws[10 * 256];
    __shared__ float hsm[128 * 65];

    const int tid   = threadIdx.x;
    const int t     = blockIdx.x;
    const int bbase = blockIdx.y * 128;

#pragma unroll
    for (int u = 0; u < 10; ++u) ws[tid + 256 * u] = roW[tid + 256 * u];

    const int bl = tid >> 1;
    const int ob = (tid & 1) * 5;
    float acc[5] = {0.f, 0.f, 0.f, 0.f, 0.f};

    for (int sc = 0; sc < 4; ++sc) {
        __syncthreads();
#pragma unroll
        for (int u = 0; u < 8; ++u) {
            int e  = tid + 256 * u;
            int rb = e >> 4;
            int k4 = (e & 15) << 2;
            float4 v = *reinterpret_cast<const float4*>(
                &g_hidden[(size_t)t * (B_ * S_) + (bbase + rb) * 256 + sc * 64 + k4]);
            hsm[rb * 65 + k4 + 0] = v.x;
            hsm[rb * 65 + k4 + 1] = v.y;
            hsm[rb * 65 + k4 + 2] = v.z;
            hsm[rb * 65 + k4 + 3] = v.w;
        }
        __syncthreads();
#pragma unroll 8
        for (int s = 0; s < 64; ++s) {
            float a = hsm[bl * 65 + s];
#pragma unroll
            for (int j = 0; j < 5; ++j)
                acc[j] = fmaf(a, ws[(ob + j) * 256 + sc * 64 + s], acc[j]);
        }
    }

    const int b = bbase + bl;
    size_t o = ((size_t)b * (T_ + 1) + t) * OUT_ + ob;
#pragma unroll
    for (int j = 0; j < 5; ++j)
        out[o + j] = acc[j] + __ldg(rob + ob + j);
}

// ---------------------------------------------------------------------------
// Launch: 4 graph nodes (split_w3, init, persistent steps, readout).
// ---------------------------------------------------------------------------
extern "C" void kernel_launch(void* const* d_in, const int* in_sizes, int n_in,
                              void* d_out, int out_size)
{
    const float* x0      = (const float*)d_in[0];
    const float* logsigs = (const float*)d_in[1];
    const float* iW1     = (const float*)d_in[2];
    const float* ib1     = (const float*)d_in[3];
    const float* iW2     = (const float*)d_in[4];
    const float* ib2     = (const float*)d_in[5];
    const float* iW3     = (const float*)d_in[6];
    const float* ib3     = (const float*)d_in[7];
    const float* vW1     = (const float*)d_in[8];
    const float* vb1     = (const float*)d_in[9];
    const float* vW2     = (const float*)d_in[10];
    const float* vb2     = (const float*)d_in[11];
    const float* vW3     = (const float*)d_in[12];
    const float* vb3     = (const float*)d_in[13];
    const float* roW     = (const float*)d_in[14];
    const float* rob     = (const float*)d_in[15];
    float* out = (float*)d_out;

    cudaFuncSetAttribute(step_kernel,
                         cudaFuncAttributeMaxDynamicSharedMemorySize, SMEM_BYTES);

    split_w3_kernel<<<NW3, 256>>>(vW3);
    init_kernel<<<64, 256>>>(x0, iW1, ib1, iW2, ib2, iW3, ib3);
    step_kernel<<<NBLK, 256, SMEM_BYTES>>>(vW1, vb1, vW2, vb2, vb3, logsigs);
    readout_kernel<<<dim3(T_ + 1, 2), 256>>>(roW, rob, out);
}

// round 13
// speedup vs baseline: 1.0016x; 1.0016x over previous
#include <cuda_runtime.h>
#include <cuda_bf16.h>
#include <cstdint>

// ---------------------------------------------------------------------------
// Problem constants
// ---------------------------------------------------------------------------
#define B_    256
#define T_    512
#define S_    256
#define L_    36
#define DIN_  8
#define OUT_  10
#define W_    256
#define NBLK  128        // persistent grid (<=148 SMs -> one wave, co-resident)
#define NW3   (S_ * L_)  // 9216

// M-phase smem layout (bytes) inside dynamic smem
#define AST32       20            // u32 stride per A row (40 bf16, conflict-free)
#define BST32       20
#define OFF_AS_H    0
#define OFF_AS_L    10240
#define OFF_BS_H    20480
#define OFF_BS_L    32000
#define OFF_LSS     43520
#define OFF_BSH     61952
#define SMEM_BYTES  62528

// ---------------------------------------------------------------------------
// Device scratch (allocation-free: __device__ globals)
// ---------------------------------------------------------------------------
__device__ float    g_h[B_ * S_];
__device__ __align__(16) __nv_bfloat16 g_z2h[B_ * W_];
__device__ __align__(16) __nv_bfloat16 g_z2l[B_ * W_];
__device__ __align__(16) __nv_bfloat16 g_w3h[NW3 * W_];   // 4.7 MB
__device__ __align__(16) __nv_bfloat16 g_w3l[NW3 * W_];
__device__ float    g_hidden[(T_ + 1) * B_ * S_];          // ~134 MB
__device__ unsigned g_bar;

// ---------------------------------------------------------------------------
// Math helpers
// ---------------------------------------------------------------------------
__device__ __forceinline__ float softplus_f(float x) {
    return (x > 0.f) ? (x + log1pf(__expf(-x))) : log1pf(__expf(x));
}
__device__ __forceinline__ float tanh_f(float x) {
    float e = __expf(2.f * x);
    return 1.f - __fdividef(2.f, e + 1.f);
}

// m16n8k16 bf16 MMA, fp32 accumulate (legacy tensor path on sm_103a)
__device__ __forceinline__ void mma_bf16(float* c, const unsigned* a,
                                         unsigned b0, unsigned b1) {
    asm volatile(
        "mma.sync.aligned.m16n8k16.row.col.f32.bf16.bf16.f32 "
        "{%0,%1,%2,%3}, {%4,%5,%6,%7}, {%8,%9}, {%0,%1,%2,%3};"
        : "+f"(c[0]), "+f"(c[1]), "+f"(c[2]), "+f"(c[3])
        : "r"(a[0]), "r"(a[1]), "r"(a[2]), "r"(a[3]), "r"(b0), "r"(b1));
}

// ---------------------------------------------------------------------------
// Software grid barrier (all NBLK blocks co-resident).
// ---------------------------------------------------------------------------
__device__ __forceinline__ void grid_barrier(unsigned target) {
    __syncthreads();
    if (threadIdx.x == 0) {
        __threadfence();
        atomicAdd(&g_bar, 1u);
        while (*((volatile unsigned*)&g_bar) < target) { __nanosleep(32); }
        __threadfence();
    }
    __syncthreads();
}

// ---------------------------------------------------------------------------
// Generic 4-row x (256 -> 256) dense layer (NT dot, W row-major [out][in]).
// ---------------------------------------------------------------------------
__device__ __forceinline__ void layer256(const float* __restrict__ in_s,
                                         float* __restrict__ out_s,
                                         const float* __restrict__ W,
                                         const float* __restrict__ bias,
                                         float* __restrict__ wtile,
                                         int tid, bool do_softplus)
{
    const int lane = tid & 31;
    const int warp = tid >> 5;
    const int r    = warp >> 1;
    const int half = warp & 1;
    int col[4];
#pragma unroll
    for (int j = 0; j < 4; ++j) col[j] = lane + 32 * half + 64 * j;

    float acc[4] = {0.f, 0.f, 0.f, 0.f};

    for (int kc = 0; kc < 8; ++kc) {
        __syncthreads();
#pragma unroll
        for (int u = 0; u < 8; ++u) {
            int e  = tid + 256 * u;
            int w  = e >> 3;
            int k4 = (e & 7) << 2;
            float4 v = *reinterpret_cast<const float4*>(W + w * 256 + kc * 32 + k4);
            *reinterpret_cast<float4*>(wtile + w * 36 + k4) = v;
        }
        __syncthreads();
#pragma unroll
        for (int kg = 0; kg < 8; ++kg) {
            float4 a = *reinterpret_cast<const float4*>(in_s + r * 256 + kc * 32 + kg * 4);
#pragma unroll
            for (int j = 0; j < 4; ++j) {
                float4 b = *reinterpret_cast<const float4*>(wtile + col[j] * 36 + kg * 4);
                acc[j] = fmaf(a.x, b.x, acc[j]);
                acc[j] = fmaf(a.y, b.y, acc[j]);
                acc[j] = fmaf(a.z, b.z, acc[j]);
                acc[j] = fmaf(a.w, b.w, acc[j]);
            }
        }
    }
    __syncthreads();
#pragma unroll
    for (int j = 0; j < 4; ++j) {
        float v = acc[j] + __ldg(bias + col[j]);
        if (do_softplus) v = softplus_f(v);
        out_s[r * 256 + col[j]] = v;
    }
}

// ---------------------------------------------------------------------------
// W3 split kernel (runs once per call): w = hi + lo in bf16.
// ---------------------------------------------------------------------------
__global__ void __launch_bounds__(256)
split_w3_kernel(const float* __restrict__ vW3)
{
    int i = blockIdx.x * 256 + threadIdx.x;   // grid = NW3 (9216) blocks
    float w = vW3[i];
    __nv_bfloat16 hi = __float2bfloat16(w);
    float lo = w - __bfloat162float(hi);
    g_w3h[i] = hi;
    g_w3l[i] = __float2bfloat16(lo);
}

// ---------------------------------------------------------------------------
// Init kernel: h0 = initMLP(x0) -> g_h, g_hidden[0]; resets g_bar.
// ---------------------------------------------------------------------------
__global__ void __launch_bounds__(256)
init_kernel(const float* __restrict__ x0,
            const float* __restrict__ iW1, const float* __restrict__ ib1,
            const float* __restrict__ iW2, const float* __restrict__ ib2,
            const float* __restrict__ iW3, const float* __restrict__ ib3)
{
    __shared__ __align__(16) float wtile[256 * 36];
    __shared__ __align__(16) float buf0[4 * 256];
    __shared__ __align__(16) float buf1[4 * 256];
    __shared__ float sx0[4 * 8];

    const int tid  = threadIdx.x;
    const int row0 = blockIdx.x * 4;

    if (blockIdx.x == 0 && tid == 0) g_bar = 0u;

    if (tid < 32) sx0[tid] = x0[row0 * DIN_ + tid];
#pragma unroll
    for (int u = 0; u < 8; ++u) wtile[tid + 256 * u] = iW1[tid + 256 * u];
    __syncthreads();

    {
        const int lane = tid & 31, warp = tid >> 5;
        const int r = warp >> 1, half = warp & 1;
#pragma unroll
        for (int j = 0; j < 4; ++j) {
            int c = lane + 32 * half + 64 * j;
            float acc = 0.f;
#pragma unroll
            for (int k = 0; k < 8; ++k)
                acc = fmaf(sx0[r * 8 + k], wtile[c * 8 + k], acc);
            buf0[r * 256 + c] = softplus_f(acc + __ldg(ib1 + c));
        }
    }
    layer256(buf0, buf1, iW2, ib2, wtile, tid, true);
    layer256(buf1, buf0, iW3, ib3, wtile, tid, false);
    __syncthreads();
#pragma unroll
    for (int u = 0; u < 4; ++u) {
        int e = tid + 256 * u;
        float v = buf0[e];
        g_h[row0 * 256 + e] = v;
        g_hidden[row0 * 256 + e] = v;
    }
}

// ---------------------------------------------------------------------------
// Persistent step kernel. grid = 128 x 256, dynamic smem SMEM_BYTES.
//
// Phase Z (blocks 0..63): z2 = sp(sp(h W1^T+b1) W2^T+b2); store bf16 hi/lo.
// Phase M (all blocks): C = z2 @ W3^T via bf16-split mma.sync (3 terms);
//   tanh + bias + l-contraction epilogue; h update; hidden store.
//   Block tile 128 rows x 144 cols; warp = 32 rows x 72 cols (2x9 m16n8).
// ---------------------------------------------------------------------------
__global__ void __launch_bounds__(256, 1)
step_kernel(const float* __restrict__ vW1, const float* __restrict__ vb1,
            const float* __restrict__ vW2, const float* __restrict__ vb2,
            const float* __restrict__ vb3, const float* __restrict__ logsigs)
{
    extern __shared__ __align__(16) unsigned char smem_raw[];

    const int tid = threadIdx.x;
    const int bid = blockIdx.x;

    // --- Z-phase carve (f32) ---
    float* wtile = reinterpret_cast<float*>(smem_raw);            // 9216 f32
    float* buf0  = wtile + 9216;                                  // 1024
    float* buf1  = wtile + 10240;                                 // 1024

    // --- M-phase carve ---
    unsigned* As_h = reinterpret_cast<unsigned*>(smem_raw + OFF_AS_H);  // 128x20
    unsigned* As_l = reinterpret_cast<unsigned*>(smem_raw + OFF_AS_L);
    unsigned* Bs_h = reinterpret_cast<unsigned*>(smem_raw + OFF_BS_H);  // 144x20
    unsigned* Bs_l = reinterpret_cast<unsigned*>(smem_raw + OFF_BS_L);
    float*    lss  = reinterpret_cast<float*>(smem_raw + OFF_LSS);      // 128x36
    float*    bsh  = reinterpret_cast<float*>(smem_raw + OFF_BSH);      // 144

    const unsigned* z2h32 = reinterpret_cast<const unsigned*>(g_z2h);   // [256][128]
    const unsigned* z2l32 = reinterpret_cast<const unsigned*>(g_z2l);
    const unsigned* w3h32 = reinterpret_cast<const unsigned*>(g_w3h);   // [9216][128]
    const unsigned* w3l32 = reinterpret_cast<const unsigned*>(g_w3l);

    // --- M-phase geometry ---
    const int lane = tid & 31;
    const int wrp  = tid >> 5;
    const int mg   = wrp & 3;          // m-group: 32 rows
    const int nh   = wrp >> 2;         // n-half: 72 cols
    const int gr   = lane >> 2;
    const int lq   = lane & 3;
    const int row0m = (bid & 1) * 128;
    const int n0    = (bid >> 1) * 144;
    const int s0    = (bid >> 1) * 4;
    const int nh72  = nh * 72;

    // staging assignments
    const int st_ar = tid >> 1;             // A row 0..127
    const int st_ak = (tid & 1) * 8;        // u32 offset {0,8}
    int  sb_r[3], sb_k[3]; bool sb_on[3];
#pragma unroll
    for (int u = 0; u < 3; ++u) {
        int idx  = tid + 256 * u;
        sb_on[u] = (idx < 576);
        sb_r[u]  = idx >> 2;                // B row 0..143
        sb_k[u]  = (idx & 3) * 4;           // u32 offset {0,4,8,12}
    }

    unsigned tgt = 0u;

    for (int t = 0; t < T_; ++t) {
        // =================== Phase Z (blocks 0..63) =======================
        if (bid < 64) {
            const int row0 = bid * 4;
#pragma unroll
            for (int u = 0; u < 4; ++u) {
                int e = tid + 256 * u;
                buf0[e] = g_h[row0 * 256 + e];
            }
            layer256(buf0, buf1, vW1, vb1, wtile, tid, true);
            layer256(buf1, buf0, vW2, vb2, wtile, tid, true);
            __syncthreads();
#pragma unroll
            for (int u = 0; u < 4; ++u) {
                int e = tid + 256 * u;
                float v = buf0[e];
                __nv_bfloat16 hi = __float2bfloat16(v);
                float lo = v - __bfloat162float(hi);
                g_z2h[row0 * 256 + e] = hi;
                g_z2l[row0 * 256 + e] = __float2bfloat16(lo);
            }
        }
        tgt += NBLK; grid_barrier(tgt);

        // =================== Phase M (all blocks) =========================
        for (int idx = tid; idx < 128 * 36; idx += 256) {
            int rb = idx / 36;
            int l  = idx - rb * 36;
            lss[idx] = logsigs[((size_t)(row0m + rb) * T_ + t) * L_ + l];
        }
        if (tid < 144) bsh[tid] = __ldg(vb3 + n0 + tid);

        float acc[2][9][4];
#pragma unroll
        for (int mf = 0; mf < 2; ++mf)
#pragma unroll
            for (int nf = 0; nf < 9; ++nf)
#pragma unroll
                for (int c = 0; c < 4; ++c) acc[mf][nf][c] = 0.f;

        // prefetch chunk 0 (k32 = 16 u32 per row)
        uint4 pAh[2], pAl[2], pBh[3], pBl[3];
        {
            const unsigned* ph = &z2h32[(row0m + st_ar) * 128 + st_ak];
            const unsigned* pl = &z2l32[(row0m + st_ar) * 128 + st_ak];
            pAh[0] = *reinterpret_cast<const uint4*>(ph);
            pAh[1] = *reinterpret_cast<const uint4*>(ph + 4);
            pAl[0] = *reinterpret_cast<const uint4*>(pl);
            pAl[1] = *reinterpret_cast<const uint4*>(pl + 4);
#pragma unroll
            for (int u = 0; u < 3; ++u)
                if (sb_on[u]) {
                    pBh[u] = *reinterpret_cast<const uint4*>(
                        &w3h32[(size_t)(n0 + sb_r[u]) * 128 + sb_k[u]]);
                    pBl[u] = *reinterpret_cast<const uint4*>(
                        &w3l32[(size_t)(n0 + sb_r[u]) * 128 + sb_k[u]]);
                }
        }

        for (int kc = 0; kc < 8; ++kc) {
            __syncthreads();   // previous compute done reading tiles
            *reinterpret_cast<uint4*>(&As_h[st_ar * AST32 + st_ak])     = pAh[0];
            *reinterpret_cast<uint4*>(&As_h[st_ar * AST32 + st_ak + 4]) = pAh[1];
            *reinterpret_cast<uint4*>(&As_l[st_ar * AST32 + st_ak])     = pAl[0];
            *reinterpret_cast<uint4*>(&As_l[st_ar * AST32 + st_ak + 4]) = pAl[1];
#pragma unroll
            for (int u = 0; u < 3; ++u)
                if (sb_on[u]) {
                    *reinterpret_cast<uint4*>(&Bs_h[sb_r[u] * BST32 + sb_k[u]]) = pBh[u];
                    *reinterpret_cast<uint4*>(&Bs_l[sb_r[u] * BST32 + sb_k[u]]) = pBl[u];
                }
            if (kc < 7) {
                const int ko = (kc + 1) * 16;
                const unsigned* ph = &z2h32[(row0m + st_ar) * 128 + ko + st_ak];
                const unsigned* pl = &z2l32[(row0m + st_ar) * 128 + ko + st_ak];
                pAh[0] = *reinterpret_cast<const uint4*>(ph);
                pAh[1] = *reinterpret_cast<const uint4*>(ph + 4);
                pAl[0] = *reinterpret_cast<const uint4*>(pl);
                pAl[1] = *reinterpret_cast<const uint4*>(pl + 4);
#pragma unroll
                for (int u = 0; u < 3; ++u)
                    if (sb_on[u]) {
                        pBh[u] = *reinterpret_cast<const uint4*>(
                            &w3h32[(size_t)(n0 + sb_r[u]) * 128 + ko + sb_k[u]]);
                        pBl[u] = *reinterpret_cast<const uint4*>(
                            &w3l32[(size_t)(n0 + sb_r[u]) * 128 + ko + sb_k[u]]);
                    }
            }
            __syncthreads();   // tiles ready

#pragma unroll
            for (int h = 0; h < 2; ++h) {            // two k16 halves
                const int kb = h * 8 + lq;
                unsigned ah[2][4], al[2][4];
#pragma unroll
                for (int mf = 0; mf < 2; ++mf) {
                    const int r0 = mg * 32 + mf * 16 + gr;
                    ah[mf][0] = As_h[r0 * AST32 + kb];
                    ah[mf][1] = As_h[(r0 + 8) * AST32 + kb];
                    ah[mf][2] = As_h[r0 * AST32 + kb + 4];
                    ah[mf][3] = As_h[(r0 + 8) * AST32 + kb + 4];
                    al[mf][0] = As_l[r0 * AST32 + kb];
                    al[mf][1] = As_l[(r0 + 8) * AST32 + kb];
                    al[mf][2] = As_l[r0 * AST32 + kb + 4];
                    al[mf][3] = As_l[(r0 + 8) * AST32 + kb + 4];
                }
#pragma unroll
                for (int nf = 0; nf < 9; ++nf) {
                    const int cb = (nh72 + nf * 8 + gr) * BST32 + kb;
                    unsigned bh0 = Bs_h[cb], bh1 = Bs_h[cb + 4];
                    unsigned bl0 = Bs_l[cb], bl1 = Bs_l[cb + 4];
#pragma unroll
                    for (int mf = 0; mf < 2; ++mf) {
                        mma_bf16(acc[mf][nf], ah[mf], bh0, bh1);  // hi*hi
                        mma_bf16(acc[mf][nf], ah[mf], bl0, bl1);  // hi*lo
                        mma_bf16(acc[mf][nf], al[mf], bh0, bh1);  // lo*hi
                    }
                }
            }
        }

        // ---- epilogue: bias + tanh + contract l, per MMA fragment layout ----
#pragma unroll
        for (int mf = 0; mf < 2; ++mf) {
            const int r0 = mg * 32 + mf * 16 + gr;   // local rows
            const int r1 = r0 + 8;
            float p0[2] = {0.f, 0.f}, p1[2] = {0.f, 0.f};
#pragma unroll
            for (int nf = 0; nf < 9; ++nf) {
#pragma unroll
                for (int c = 0; c < 2; ++c) {
                    int nl = nh72 + nf * 8 + 2 * lq + c;   // col in [0,144)
                    int l  = nl, sl = 0;
                    if (l >= 72) l -= 72;
                    if (l >= 36) { l -= 36; sl = 1; }
                    const float bj = bsh[nl];
                    const float v0 = tanh_f(acc[mf][nf][c]     + bj);
                    const float v1 = tanh_f(acc[mf][nf][2 + c] + bj);
                    p0[sl] = fmaf(v0, lss[r0 * 36 + l], p0[sl]);
                    p1[sl] = fmaf(v1, lss[r1 * 36 + l], p1[sl]);
                }
            }
#pragma unroll
            for (int sl = 0; sl < 2; ++sl) {
                p0[sl] += __shfl_xor_sync(0xffffffffu, p0[sl], 1);
                p0[sl] += __shfl_xor_sync(0xffffffffu, p0[sl], 2);
                p1[sl] += __shfl_xor_sync(0xffffffffu, p1[sl], 1);
                p1[sl] += __shfl_xor_sync(0xffffffffu, p1[sl], 2);
            }
            if (lq == 0) {
                const int b0g = row0m + r0;
                const int b1g = row0m + r1;
#pragma unroll
                for (int sl = 0; sl < 2; ++sl) {
                    const int sg = s0 + nh * 2 + sl;
                    float h0 = g_h[b0g * 256 + sg] + p0[sl];
                    float h1 = g_h[b1g * 256 + sg] + p1[sl];
                    g_h[b0g * 256 + sg] = h0;
                    g_h[b1g * 256 + sg] = h1;
                    g_hidden[(size_t)(t + 1) * (B_ * S_) + b0g * 256 + sg] = h0;
                    g_hidden[(size_t)(t + 1) * (B_ * S_) + b1g * 256 + sg] = h1;
                }
            }
        }
        tgt += NBLK; grid_barrier(tgt);
    }
}

// ---------------------------------------------------------------------------
// Readout: out[b,t,o] = sum_s hidden[t,b,s] * ro_W[o,s] + ro_b[o]
// ---------------------------------------------------------------------------
__global__ void __launch_bounds__(256)
readout_kernel(const float* __restrict__ roW, const float* __restrict__ rob,
               float* __restrict__ out)
{
    __shared__ float ws[10 * 256];
    __shared__ float hsm[128 * 65];

    const int tid   = threadIdx.x;
    const int t     = blockIdx.x;
    const int bbase = blockIdx.y * 128;

#pragma unroll
    for (int u = 0; u < 10; ++u) ws[tid + 256 * u] = roW[tid + 256 * u];

    const int bl = tid >> 1;
    const int ob = (tid & 1) * 5;
    float acc[5] = {0.f, 0.f, 0.f, 0.f, 0.f};

    for (int sc = 0; sc < 4; ++sc) {
        __syncthreads();
#pragma unroll
        for (int u = 0; u < 8; ++u) {
            int e  = tid + 256 * u;
            int rb = e >> 4;
            int k4 = (e & 15) << 2;
            float4 v = *reinterpret_cast<const float4*>(
                &g_hidden[(size_t)t * (B_ * S_) + (bbase + rb) * 256 + sc * 64 + k4]);
            hsm[rb * 65 + k4 + 0] = v.x;
            hsm[rb * 65 + k4 + 1] = v.y;
            hsm[rb * 65 + k4 + 2] = v.z;
            hsm[rb * 65 + k4 + 3] = v.w;
        }
        __syncthreads();
#pragma unroll 8
        for (int s = 0; s < 64; ++s) {
            float a = hsm[bl * 65 + s];
#pragma unroll
            for (int j = 0; j < 5; ++j)
                acc[j] = fmaf(a, ws[(ob + j) * 256 + sc * 64 + s], acc[j]);
        }
    }

    const int b = bbase + bl;
    size_t o = ((size_t)b * (T_ + 1) + t) * OUT_ + ob;
#pragma unroll
    for (int j = 0; j < 5; ++j)
        out[o + j] = acc[j] + __ldg(rob + ob + j);
}

// ---------------------------------------------------------------------------
// Launch: 4 graph nodes (split_w3, init, persistent steps, readout).
// ---------------------------------------------------------------------------
extern "C" void kernel_launch(void* const* d_in, const int* in_sizes, int n_in,
                              void* d_out, int out_size)
{
    const float* x0      = (const float*)d_in[0];
    const float* logsigs = (const float*)d_in[1];
    const float* iW1     = (const float*)d_in[2];
    const float* ib1     = (const float*)d_in[3];
    const float* iW2     = (const float*)d_in[4];
    const float* ib2     = (const float*)d_in[5];
    const float* iW3     = (const float*)d_in[6];
    const float* ib3     = (const float*)d_in[7];
    const float* vW1     = (const float*)d_in[8];
    const float* vb1     = (const float*)d_in[9];
    const float* vW2     = (const float*)d_in[10];
    const float* vb2     = (const float*)d_in[11];
    const float* vW3     = (const float*)d_in[12];
    const float* vb3     = (const float*)d_in[13];
    const float* roW     = (const float*)d_in[14];
    const float* rob     = (const float*)d_in[15];
    float* out = (float*)d_out;

    cudaFuncSetAttribute(step_kernel,
                         cudaFuncAttributeMaxDynamicSharedMemorySize, SMEM_BYTES);

    split_w3_kernel<<<NW3, 256>>>(vW3);
    init_kernel<<<64, 256>>>(x0, iW1, ib1, iW2, ib2, iW3, ib3);
    step_kernel<<<NBLK, 256, SMEM_BYTES>>>(vW1, vb1, vW2, vb2, vb3, logsigs);
    readout_kernel<<<dim3(T_ + 1, 2), 256>>>(roW, rob, out);
}